// round 1
// baseline (speedup 1.0000x reference)
#include <cuda_runtime.h>
#include <math.h>

#define BB 16
#define AA 8732
#define CC 91
#define NC 90
#define KK 400
#define NCAND (NC*KK)   /* 36000 */
#define DD 200
#define IMGV 300.0f
#define OFFV 302.0f
#define THRESH 0.01f
#define NMSV 0.45f
#define NEGINF (-1e30f)
#define CLIPV 4.135166556742356f

// ---------------- scratch (device globals; no allocation) ----------------
__device__ float  g_probsT[(size_t)BB*CC*AA];   // class-major probs, ~50.9MB
__device__ float4 g_boxes[BB*AA];               // decoded clipped boxes
__device__ float  g_candVal[BB*NCAND];
__device__ int    g_candIdx[BB*NCAND];
__device__ float4 g_candBox[BB*NCAND];
__device__ float  g_survVal[(size_t)BB*NC*KK];
__device__ int    g_survK[(size_t)BB*NC*KK];
__device__ int    g_survCnt[BB*NC];
__device__ int    g_keepFlat[BB*DD];

// ---------------- kernel 1: box decode ----------------
__global__ void decode_kernel(const float* __restrict__ rel,
                              const float* __restrict__ anchors) {
    int i = blockIdx.x * blockDim.x + threadIdx.x;
    if (i >= BB*AA) return;
    int a = i % AA;
    float4 an = ((const float4*)anchors)[a];
    float4 rg = ((const float4*)rel)[i];
    float wa  = __fsub_rn(an.z, an.x);
    float ha  = __fsub_rn(an.w, an.y);
    float cxa = __fadd_rn(an.x, __fmul_rn(0.5f, wa));
    float cya = __fadd_rn(an.y, __fmul_rn(0.5f, ha));
    float dx  = __fdiv_rn(rg.x, 10.0f);
    float dy  = __fdiv_rn(rg.y, 10.0f);
    float dw  = fminf(__fdiv_rn(rg.z, 5.0f), CLIPV);
    float dh  = fminf(__fdiv_rn(rg.w, 5.0f), CLIPV);
    float cx  = __fadd_rn(__fmul_rn(dx, wa), cxa);
    float cy  = __fadd_rn(__fmul_rn(dy, ha), cya);
    float w   = __fmul_rn(expf(dw), wa);
    float h   = __fmul_rn(expf(dh), ha);
    float4 o;
    o.x = fminf(fmaxf(__fsub_rn(cx, __fmul_rn(0.5f, w)), 0.0f), IMGV);
    o.y = fminf(fmaxf(__fsub_rn(cy, __fmul_rn(0.5f, h)), 0.0f), IMGV);
    o.z = fminf(fmaxf(__fadd_rn(cx, __fmul_rn(0.5f, w)), 0.0f), IMGV);
    o.w = fminf(fmaxf(__fadd_rn(cy, __fmul_rn(0.5f, h)), 0.0f), IMGV);
    g_boxes[i] = o;
}

// ---------------- kernel 2: softmax, transposed store ----------------
// tile of 128 anchors per block; smem [91][129] to avoid bank conflicts.
__global__ void softmax_kernel(const float* __restrict__ logits) {
    __shared__ float s[CC * 129];
    int b = blockIdx.y;
    int a0 = blockIdx.x * 128;
    int na = AA - a0; if (na > 128) na = 128;
    int tid = threadIdx.x;
    const float* base = logits + (size_t)(b*AA + a0) * CC;
    for (int idx = tid; idx < na * CC; idx += 128) {
        int al = idx / CC;
        int c  = idx - al * CC;
        s[c * 129 + al] = base[idx];
    }
    __syncthreads();
    if (tid < na) {
        float m = NEGINF;
        for (int c = 0; c < CC; c++) m = fmaxf(m, s[c*129 + tid]);
        float sum = 0.0f;
        for (int c = 0; c < CC; c++) {
            float e = expf(__fsub_rn(s[c*129 + tid], m));
            s[c*129 + tid] = e;
            sum = __fadd_rn(sum, e);
        }
        for (int c = 0; c < CC; c++)
            s[c*129 + tid] = __fdiv_rn(s[c*129 + tid], sum);
    }
    __syncthreads();
    for (int c = 0; c < CC; c++) {
        if (tid < na)
            g_probsT[((size_t)(b*CC + c))*AA + a0 + tid] = s[c*129 + tid];
    }
}

// ---------------- kernel 3: per-(b,class) top-400 ----------------
// radix select (4 x 8-bit MSB passes) on flip-float keys, then bitonic sort
// of 512 composite (valkey<<32 | ~anchor) keys -> (val desc, idx asc).
__global__ void topk_kernel() {
    __shared__ unsigned keys[AA];
    __shared__ unsigned long long sel[512];
    __shared__ int hist[256];
    __shared__ unsigned s_prefix, s_pmask;
    __shared__ int s_need, s_nsel, s_neq;
    int crow = blockIdx.x;   // class-1
    int b    = blockIdx.y;
    int tid  = threadIdx.x;

    const float* col = g_probsT + ((size_t)(b*CC + crow + 1)) * AA;
    for (int a = tid; a < AA; a += 256) {
        float p = col[a];
        float mval = (p > THRESH) ? p : -1.0f;
        unsigned u = __float_as_uint(mval);
        keys[a] = (u & 0x80000000u) ? ~u : (u | 0x80000000u);
    }
    if (tid == 0) { s_prefix = 0; s_pmask = 0; s_need = KK; s_nsel = 0; s_neq = 0; }
    __syncthreads();

    for (int pass = 0; pass < 4; pass++) {
        int shift = 24 - 8*pass;
        if (tid < 256) hist[tid] = 0;
        __syncthreads();
        unsigned pm = s_pmask, pf = s_prefix;
        for (int a = tid; a < AA; a += 256) {
            unsigned k = keys[a];
            if ((k & pm) == pf) atomicAdd(&hist[(k >> shift) & 255], 1);
        }
        __syncthreads();
        if (tid == 0) {
            int cum = 0, need = s_need;
            for (int d = 255; d >= 0; --d) {
                int h = hist[d];
                if (cum + h >= need) {
                    s_prefix = pf | ((unsigned)d << shift);
                    s_pmask  = pm | (255u << shift);
                    s_need   = need - cum;
                    break;
                }
                cum += h;
            }
        }
        __syncthreads();
    }
    unsigned V = s_prefix;
    int needT  = s_need;

    for (int a = tid; a < AA; a += 256) {
        unsigned k = keys[a];
        if (k > V) {
            int pos = atomicAdd(&s_nsel, 1);
            sel[pos] = ((unsigned long long)k << 32) | (unsigned)(0xFFFFFFFFu - (unsigned)a);
        } else if (k == V) {
            int e = atomicAdd(&s_neq, 1);
            if (e < needT) {
                int pos = atomicAdd(&s_nsel, 1);
                sel[pos] = ((unsigned long long)k << 32) | (unsigned)(0xFFFFFFFFu - (unsigned)a);
            }
        }
    }
    __syncthreads();
    int nsel = s_nsel;
    for (int p = nsel + tid; p < 512; p += 256) sel[p] = 0ULL;
    __syncthreads();

    // bitonic sort 512, descending
    for (int k2 = 2; k2 <= 512; k2 <<= 1) {
        for (int j = k2 >> 1; j > 0; j >>= 1) {
            for (int i = tid; i < 512; i += 256) {
                int l = i ^ j;
                if (l > i) {
                    unsigned long long x = sel[i], y = sel[l];
                    bool desc = ((i & k2) == 0);
                    if (desc ? (x < y) : (x > y)) { sel[i] = y; sel[l] = x; }
                }
            }
            __syncthreads();
        }
    }

    for (int k = tid; k < KK; k += 256) {
        unsigned long long e = sel[k];
        unsigned vk = (unsigned)(e >> 32);
        unsigned a  = 0xFFFFFFFFu - (unsigned)(e & 0xFFFFFFFFu);
        unsigned u  = (vk & 0x80000000u) ? (vk & 0x7FFFFFFFu) : ~vk;
        float val   = __uint_as_float(u);
        size_t o = (size_t)b*NCAND + crow*KK + k;
        if (k < nsel && a < AA) {
            g_candVal[o] = val;
            g_candIdx[o] = (int)a;
            g_candBox[o] = g_boxes[(size_t)b*AA + a];
        } else {
            g_candVal[o] = -1.0f;
            g_candIdx[o] = 0;
            g_candBox[o] = make_float4(0.f,0.f,0.f,0.f);
        }
    }
}

// ---------------- kernel 4: per-(b,class) greedy NMS, one warp each ----------------
__global__ void classnms_kernel() {
    __shared__ float s_ob[4][KK*4];
    __shared__ float s_area[4][KK];
    __shared__ float s_val[4][KK];
    __shared__ unsigned s_sup[4][16];
    int w    = threadIdx.x >> 5;
    int lane = threadIdx.x & 31;
    int wg   = blockIdx.x * 4 + w;
    int b    = wg / NC;
    int crow = wg % NC;
    size_t base = (size_t)b*NCAND + (size_t)crow*KK;
    float off = __fmul_rn((float)(crow + 1), OFFV);

    for (int i = lane; i < KK; i += 32) {
        float4 bx = g_candBox[base + i];
        float o0 = __fadd_rn(bx.x, off);
        float o1 = __fadd_rn(bx.y, off);
        float o2 = __fadd_rn(bx.z, off);
        float o3 = __fadd_rn(bx.w, off);
        s_ob[w][i*4+0] = o0; s_ob[w][i*4+1] = o1;
        s_ob[w][i*4+2] = o2; s_ob[w][i*4+3] = o3;
        s_area[w][i] = __fmul_rn(__fsub_rn(o2, o0), __fsub_rn(o3, o1));
        s_val[w][i]  = g_candVal[base + i];
    }
    if (lane < 16) s_sup[w][lane] = 0;
    __syncwarp();

    int cnt = 0;
    for (int i = 0; i < KK; i++) {
        float v = s_val[w][i];
        if (v <= THRESH) break;                       // sorted desc -> done
        if ((s_sup[w][i >> 5] >> (i & 31)) & 1) continue;
        if (lane == 0) {
            g_survVal[(size_t)(b*NC + crow)*KK + cnt] = v;
            g_survK  [(size_t)(b*NC + crow)*KK + cnt] = i;
        }
        cnt++;
        float ox1 = s_ob[w][i*4+0], oy1 = s_ob[w][i*4+1];
        float ox2 = s_ob[w][i*4+2], oy2 = s_ob[w][i*4+3];
        float a1  = s_area[w][i];
        for (int word = i >> 5; word < 13; word++) {
            int j = word*32 + lane;
            bool sj = false;
            if (j > i && j < KK) {
                float jx1 = s_ob[w][j*4+0], jy1 = s_ob[w][j*4+1];
                float jx2 = s_ob[w][j*4+2], jy2 = s_ob[w][j*4+3];
                float x1 = fmaxf(ox1, jx1), y1 = fmaxf(oy1, jy1);
                float x2 = fminf(ox2, jx2), y2 = fminf(oy2, jy2);
                float inter = __fmul_rn(fmaxf(__fsub_rn(x2, x1), 0.0f),
                                        fmaxf(__fsub_rn(y2, y1), 0.0f));
                float denom = __fadd_rn(__fsub_rn(__fadd_rn(a1, s_area[w][j]), inter), 1e-9f);
                float iou = __fdiv_rn(inter, denom);
                sj = iou > NMSV;
            }
            unsigned m = __ballot_sync(0xFFFFFFFFu, sj);
            if (lane == 0 && m) s_sup[w][word] |= m;
        }
        __syncwarp();
    }
    if (lane == 0) g_survCnt[b*NC + crow] = cnt;
}

// ---------------- kernel 5: per-image merge of survivor streams ----------------
__global__ void merge_kernel() {
    extern __shared__ char sm[];
    float* sval = (float*)sm;                       // [NC][200]
    int*   sk   = (int*)(sm + NC*200*sizeof(float));// [NC][200]
    int b = blockIdx.x, tid = threadIdx.x;
    for (int idx = tid; idx < NC*200; idx += blockDim.x) {
        int c = idx / 200, t = idx - c*200;
        int cnt = g_survCnt[b*NC + c];
        if (t < cnt) {
            sval[idx] = g_survVal[(size_t)(b*NC + c)*KK + t];
            sk[idx]   = g_survK  [(size_t)(b*NC + c)*KK + t];
        } else sval[idx] = NEGINF;
    }
    __syncthreads();
    if (tid >= 32) return;
    int lane = tid;
    int c0 = lane, c1 = lane + 32, c2 = lane + 64;
    int h0 = 0, h1 = 0, h2 = 0;
    float v0 = (c0 < NC) ? sval[c0*200] : NEGINF;
    float v1 = (c1 < NC) ? sval[c1*200] : NEGINF;
    float v2 = (c2 < NC) ? sval[c2*200] : NEGINF;
    for (int it = 0; it < DD; it++) {
        float bv = v0; int bc = c0;
        if (v1 > bv) { bv = v1; bc = c1; }
        if (v2 > bv) { bv = v2; bc = c2; }
        for (int o = 16; o > 0; o >>= 1) {
            float ov = __shfl_down_sync(0xFFFFFFFFu, bv, o);
            int   oc = __shfl_down_sync(0xFFFFFFFFu, bc, o);
            if (ov > bv || (ov == bv && oc < bc)) { bv = ov; bc = oc; }
        }
        bv = __shfl_sync(0xFFFFFFFFu, bv, 0);
        bc = __shfl_sync(0xFFFFFFFFu, bc, 0);
        if (bv <= -1e29f) {
            if (lane == 0) for (int r = it; r < DD; r++) g_keepFlat[b*DD + r] = -1;
            return;
        }
        if (lane == (bc & 31)) {
            int slot = bc >> 5;
            int h = (slot == 0) ? h0 : ((slot == 1) ? h1 : h2);
            int kkv = sk[bc*200 + h];
            g_keepFlat[b*DD + it] = bc*KK + kkv;
            h++;
            float nv = (h < 200) ? sval[bc*200 + h] : NEGINF;
            if (slot == 0)      { h0 = h; v0 = nv; }
            else if (slot == 1) { h1 = h; v1 = nv; }
            else                { h2 = h; v2 = nv; }
        }
        __syncwarp();
    }
}

// ---------------- kernel 6: output assembly (one warp per kept row) ----------------
__global__ void output_kernel(float* __restrict__ out, int mode) {
    int wg   = blockIdx.x * (blockDim.x >> 5) + (threadIdx.x >> 5);
    int lane = threadIdx.x & 31;
    if (wg >= BB*DD) return;
    int b = wg / DD, r = wg % DD;
    float* ob = 0; float* os = 0; float* ol = 0;
    if (mode == 0) {                 // full concat: boxes | scores | labels
        ob = out + (size_t)(b*DD + r)*4;
        os = out + (size_t)BB*DD*4 + (size_t)(b*DD + r)*2;
        ol = out + (size_t)BB*DD*6 + (size_t)(b*DD + r)*2;
    } else if (mode == 1) {          // boxes only
        ob = out + (size_t)(b*DD + r)*4;
    } else {                         // scores only
        os = out + (size_t)(b*DD + r)*2;
    }
    int flat = g_keepFlat[b*DD + r];
    if (flat < 0) {
        if (lane == 0) {
            if (ob) { ob[0]=0.f; ob[1]=0.f; ob[2]=0.f; ob[3]=0.f; }
            if (os) { os[0]=0.f; os[1]=0.f; }
            if (ol) { ol[0]=0.f; ol[1]=0.f; }
        }
        return;
    }
    size_t co = (size_t)b*NCAND + flat;
    if (lane == 0 && ob) {
        float4 bx = g_candBox[co];
        ob[0] = bx.x; ob[1] = bx.y; ob[2] = bx.z; ob[3] = bx.w;
    }
    if (!os && !ol) return;
    int anchor = g_candIdx[co];
    float va[3]; int ia[3];
#pragma unroll
    for (int s = 0; s < 3; s++) {
        int c = 1 + lane + 32*s;
        if (c <= NC) { va[s] = g_probsT[((size_t)(b*CC + c))*AA + anchor]; ia[s] = c; }
        else         { va[s] = NEGINF; ia[s] = 1 << 20; }
    }
    float f1v = va[0], f2v = NEGINF;
    int   f1i = ia[0], f2i = 1 << 20;
#pragma unroll
    for (int s = 1; s < 3; s++) {
        if (va[s] > f1v)      { f2v = f1v; f2i = f1i; f1v = va[s]; f1i = ia[s]; }
        else if (va[s] > f2v) { f2v = va[s]; f2i = ia[s]; }
    }
    for (int o = 16; o > 0; o >>= 1) {
        float o1v = __shfl_down_sync(0xFFFFFFFFu, f1v, o);
        int   o1i = __shfl_down_sync(0xFFFFFFFFu, f1i, o);
        float o2v = __shfl_down_sync(0xFFFFFFFFu, f2v, o);
        int   o2i = __shfl_down_sync(0xFFFFFFFFu, f2i, o);
        bool a_first = (f1v > o1v) || (f1v == o1v && f1i < o1i);
        float n1v, n2v; int n1i, n2i;
        if (a_first) {
            n1v = f1v; n1i = f1i;
            bool pick = (f2v > o1v) || (f2v == o1v && f2i < o1i);
            n2v = pick ? f2v : o1v; n2i = pick ? f2i : o1i;
        } else {
            n1v = o1v; n1i = o1i;
            bool pick = (o2v > f1v) || (o2v == f1v && o2i < f1i);
            n2v = pick ? o2v : f1v; n2i = pick ? o2i : f1i;
        }
        f1v = n1v; f1i = n1i; f2v = n2v; f2i = n2i;
    }
    if (lane == 0) {
        if (os) { os[0] = f1v; os[1] = f2v; }
        if (ol) { ol[0] = (float)f1i; ol[1] = (float)f2i; }
    }
}

// ---------------- launcher ----------------
extern "C" void kernel_launch(void* const* d_in, const int* in_sizes, int n_in,
                              void* d_out, int out_size) {
    const float* logits  = (const float*)d_in[0];   // (B, A, C)
    const float* rel     = (const float*)d_in[1];   // (B, A, 4)
    const float* anchors = (const float*)d_in[2];   // (A, 4)
    float* out = (float*)d_out;

    decode_kernel<<<(BB*AA + 127)/128, 128>>>(rel, anchors);

    dim3 gs((AA + 127)/128, BB);
    softmax_kernel<<<gs, 128>>>(logits);

    dim3 gt(NC, BB);
    topk_kernel<<<gt, 256>>>();

    classnms_kernel<<<(BB*NC)/4, 128>>>();

    (void)cudaFuncSetAttribute(merge_kernel,
                               cudaFuncAttributeMaxDynamicSharedMemorySize,
                               NC*200*8);
    merge_kernel<<<BB, 256, NC*200*8>>>();

    int mode = 0;
    if (out_size == BB*DD*8)      mode = 0;  // 25600: boxes|scores|labels
    else if (out_size == BB*DD*4) mode = 1;  // boxes only
    else                          mode = 2;  // scores only fallback
    output_kernel<<<(BB*DD)/8, 256>>>(out, mode);
}

// round 2
// speedup vs baseline: 1.4016x; 1.4016x over previous
#include <cuda_runtime.h>
#include <math.h>

#define BB 16
#define AA 8732
#define CC 91
#define NC 90
#define KK 400
#define NCAND (NC*KK)   /* 36000 */
#define DD 200
#define IMGV 300.0f
#define OFFV 302.0f
#define THRESH 0.01f
#define NMSV 0.45f
#define NEGINF (-1e30f)
#define CLIPV 4.135166556742356f
#define NW 13            /* ceil(400/32) words per class */

// ---------------- scratch (device globals; no allocation) ----------------
__device__ float  g_probsT[(size_t)BB*CC*AA];   // class-major probs, ~50.9MB
__device__ float4 g_boxes[BB*AA];               // decoded clipped boxes
__device__ float  g_candVal[BB*NCAND];
__device__ int    g_candIdx[BB*NCAND];
__device__ float4 g_candBox[BB*NCAND];
__device__ float  g_survVal[(size_t)BB*NC*KK];
__device__ int    g_survK[(size_t)BB*NC*KK];
__device__ int    g_survCnt[BB*NC];
__device__ int    g_keepFlat[BB*DD];

// ---------------- kernel 1: box decode ----------------
__global__ void decode_kernel(const float* __restrict__ rel,
                              const float* __restrict__ anchors) {
    int i = blockIdx.x * blockDim.x + threadIdx.x;
    if (i >= BB*AA) return;
    int a = i % AA;
    float4 an = ((const float4*)anchors)[a];
    float4 rg = ((const float4*)rel)[i];
    float wa  = __fsub_rn(an.z, an.x);
    float ha  = __fsub_rn(an.w, an.y);
    float cxa = __fadd_rn(an.x, __fmul_rn(0.5f, wa));
    float cya = __fadd_rn(an.y, __fmul_rn(0.5f, ha));
    float dx  = __fdiv_rn(rg.x, 10.0f);
    float dy  = __fdiv_rn(rg.y, 10.0f);
    float dw  = fminf(__fdiv_rn(rg.z, 5.0f), CLIPV);
    float dh  = fminf(__fdiv_rn(rg.w, 5.0f), CLIPV);
    float cx  = __fadd_rn(__fmul_rn(dx, wa), cxa);
    float cy  = __fadd_rn(__fmul_rn(dy, ha), cya);
    float w   = __fmul_rn(expf(dw), wa);
    float h   = __fmul_rn(expf(dh), ha);
    float4 o;
    o.x = fminf(fmaxf(__fsub_rn(cx, __fmul_rn(0.5f, w)), 0.0f), IMGV);
    o.y = fminf(fmaxf(__fsub_rn(cy, __fmul_rn(0.5f, h)), 0.0f), IMGV);
    o.z = fminf(fmaxf(__fadd_rn(cx, __fmul_rn(0.5f, w)), 0.0f), IMGV);
    o.w = fminf(fmaxf(__fadd_rn(cy, __fmul_rn(0.5f, h)), 0.0f), IMGV);
    g_boxes[i] = o;
}

// ---------------- kernel 2: softmax, transposed store ----------------
__global__ void softmax_kernel(const float* __restrict__ logits) {
    __shared__ float s[CC * 129];
    int b = blockIdx.y;
    int a0 = blockIdx.x * 128;
    int na = AA - a0; if (na > 128) na = 128;
    int tid = threadIdx.x;
    const float* base = logits + (size_t)(b*AA + a0) * CC;
    for (int idx = tid; idx < na * CC; idx += 128) {
        int al = idx / CC;
        int c  = idx - al * CC;
        s[c * 129 + al] = base[idx];
    }
    __syncthreads();
    if (tid < na) {
        float m = NEGINF;
        for (int c = 0; c < CC; c++) m = fmaxf(m, s[c*129 + tid]);
        float sum = 0.0f;
        for (int c = 0; c < CC; c++) {
            float e = expf(__fsub_rn(s[c*129 + tid], m));
            s[c*129 + tid] = e;
            sum = __fadd_rn(sum, e);
        }
        for (int c = 0; c < CC; c++)
            s[c*129 + tid] = __fdiv_rn(s[c*129 + tid], sum);
    }
    __syncthreads();
    for (int c = 0; c < CC; c++) {
        if (tid < na)
            g_probsT[((size_t)(b*CC + c))*AA + a0 + tid] = s[c*129 + tid];
    }
}

// ---------------- kernel 3: per-(b,class) top-400 ----------------
__global__ void topk_kernel() {
    __shared__ unsigned keys[AA];
    __shared__ unsigned long long sel[512];
    __shared__ int hist[256];
    __shared__ unsigned s_prefix, s_pmask;
    __shared__ int s_need, s_nsel, s_neq;
    int crow = blockIdx.x;   // class-1
    int b    = blockIdx.y;
    int tid  = threadIdx.x;

    const float* col = g_probsT + ((size_t)(b*CC + crow + 1)) * AA;
    for (int a = tid; a < AA; a += 256) {
        float p = col[a];
        float mval = (p > THRESH) ? p : -1.0f;
        unsigned u = __float_as_uint(mval);
        keys[a] = (u & 0x80000000u) ? ~u : (u | 0x80000000u);
    }
    if (tid == 0) { s_prefix = 0; s_pmask = 0; s_need = KK; s_nsel = 0; s_neq = 0; }
    __syncthreads();

    for (int pass = 0; pass < 4; pass++) {
        int shift = 24 - 8*pass;
        if (tid < 256) hist[tid] = 0;
        __syncthreads();
        unsigned pm = s_pmask, pf = s_prefix;
        for (int a = tid; a < AA; a += 256) {
            unsigned k = keys[a];
            if ((k & pm) == pf) atomicAdd(&hist[(k >> shift) & 255], 1);
        }
        __syncthreads();
        if (tid == 0) {
            int cum = 0, need = s_need;
            for (int d = 255; d >= 0; --d) {
                int h = hist[d];
                if (cum + h >= need) {
                    s_prefix = pf | ((unsigned)d << shift);
                    s_pmask  = pm | (255u << shift);
                    s_need   = need - cum;
                    break;
                }
                cum += h;
            }
        }
        __syncthreads();
    }
    unsigned V = s_prefix;
    int needT  = s_need;

    for (int a = tid; a < AA; a += 256) {
        unsigned k = keys[a];
        if (k > V) {
            int pos = atomicAdd(&s_nsel, 1);
            sel[pos] = ((unsigned long long)k << 32) | (unsigned)(0xFFFFFFFFu - (unsigned)a);
        } else if (k == V) {
            int e = atomicAdd(&s_neq, 1);
            if (e < needT) {
                int pos = atomicAdd(&s_nsel, 1);
                sel[pos] = ((unsigned long long)k << 32) | (unsigned)(0xFFFFFFFFu - (unsigned)a);
            }
        }
    }
    __syncthreads();
    int nsel = s_nsel;
    for (int p = nsel + tid; p < 512; p += 256) sel[p] = 0ULL;
    __syncthreads();

    // bitonic sort 512, descending
    for (int k2 = 2; k2 <= 512; k2 <<= 1) {
        for (int j = k2 >> 1; j > 0; j >>= 1) {
            for (int i = tid; i < 512; i += 256) {
                int l = i ^ j;
                if (l > i) {
                    unsigned long long x = sel[i], y = sel[l];
                    bool desc = ((i & k2) == 0);
                    if (desc ? (x < y) : (x > y)) { sel[i] = y; sel[l] = x; }
                }
            }
            __syncthreads();
        }
    }

    for (int k = tid; k < KK; k += 256) {
        unsigned long long e = sel[k];
        unsigned vk = (unsigned)(e >> 32);
        unsigned a  = 0xFFFFFFFFu - (unsigned)(e & 0xFFFFFFFFu);
        unsigned u  = (vk & 0x80000000u) ? (vk & 0x7FFFFFFFu) : ~vk;
        float val   = __uint_as_float(u);
        size_t o = (size_t)b*NCAND + crow*KK + k;
        if (k < nsel && a < AA) {
            g_candVal[o] = val;
            g_candIdx[o] = (int)a;
            g_candBox[o] = g_boxes[(size_t)b*AA + a];
        } else {
            g_candVal[o] = -1.0f;
            g_candIdx[o] = 0;
            g_candBox[o] = make_float4(0.f,0.f,0.f,0.f);
        }
    }
}

// ---------------- kernel 4: per-(b,class) greedy NMS, register-resident ----------------
// One warp per (b,class). Each lane owns NW=13 candidates (j = t*32+lane):
// coords/area/val + a 13-bit suppression mask, all in registers. The pivot
// walk is unrolled over words so all register indexing is static; pivot data
// is broadcast via shfl. Survivor count capped at DD (=200), which is exact
// because the global merge can never take more than DD from a single class.
__global__ void __launch_bounds__(128) classnms_kernel() {
    const unsigned FULL = 0xFFFFFFFFu;
    int w    = threadIdx.x >> 5;
    int lane = threadIdx.x & 31;
    int wg   = blockIdx.x * 4 + w;
    int b    = wg / NC;
    int crow = wg % NC;
    size_t base = (size_t)b*NCAND + (size_t)crow*KK;
    size_t sbase = (size_t)(b*NC + crow)*KK;
    float off = __fmul_rn((float)(crow + 1), OFFV);

    float bx1[NW], by1[NW], bx2[NW], by2[NW], ar[NW], vv[NW];
#pragma unroll
    for (int t = 0; t < NW; t++) {
        int j = t*32 + lane;
        float4 bx = make_float4(0.f,0.f,0.f,0.f);
        float v = -1.0f;
        if (j < KK) { bx = g_candBox[base + j]; v = g_candVal[base + j]; }
        float o0 = __fadd_rn(bx.x, off);
        float o1 = __fadd_rn(bx.y, off);
        float o2 = __fadd_rn(bx.z, off);
        float o3 = __fadd_rn(bx.w, off);
        bx1[t] = o0; by1[t] = o1; bx2[t] = o2; by2[t] = o3;
        ar[t]  = __fmul_rn(__fsub_rn(o2, o0), __fsub_rn(o3, o1));
        vv[t]  = v;
    }

    unsigned sup = 0;     // bit t: candidate t*32+lane suppressed
    int cnt = 0;

#pragma unroll
    for (int t = 0; t < NW; t++) {
        for (int l = 0; l < 32; l++) {
            const int i = t*32 + l;
            if (i >= KK) goto done;
            float v = __shfl_sync(FULL, vv[t], l);
            if (v <= THRESH) goto done;                 // sorted desc
            unsigned supl = __shfl_sync(FULL, sup, l);
            if ((supl >> t) & 1u) continue;
            if (lane == 0) {
                g_survVal[sbase + cnt] = v;
                g_survK  [sbase + cnt] = i;
            }
            cnt++;
            if (cnt >= DD) goto done;                   // merge needs <=200/class
            float px1 = __shfl_sync(FULL, bx1[t], l);
            float py1 = __shfl_sync(FULL, by1[t], l);
            float px2 = __shfl_sync(FULL, bx2[t], l);
            float py2 = __shfl_sync(FULL, by2[t], l);
            float pa  = __shfl_sync(FULL, ar[t],  l);
#pragma unroll
            for (int t2 = t; t2 < NW; t2++) {
                float x1 = fmaxf(px1, bx1[t2]);
                float y1 = fmaxf(py1, by1[t2]);
                float x2 = fminf(px2, bx2[t2]);
                float y2 = fminf(py2, by2[t2]);
                float inter = __fmul_rn(fmaxf(__fsub_rn(x2, x1), 0.0f),
                                        fmaxf(__fsub_rn(y2, y1), 0.0f));
                float denom = __fadd_rn(__fsub_rn(__fadd_rn(pa, ar[t2]), inter), 1e-9f);
                float iou = __fdiv_rn(inter, denom);
                bool later = (t2 > t) || (lane > l);    // only j > i can be suppressed
                if (iou > NMSV && later) sup |= (1u << t2);
            }
        }
    }
done:
    if (lane == 0) g_survCnt[b*NC + crow] = cnt;
}

// ---------------- kernel 5: per-image merge of survivor streams ----------------
__global__ void merge_kernel() {
    extern __shared__ char sm[];
    float* sval = (float*)sm;                       // [NC][200]
    int*   sk   = (int*)(sm + NC*200*sizeof(float));// [NC][200]
    int b = blockIdx.x, tid = threadIdx.x;
    for (int idx = tid; idx < NC*200; idx += blockDim.x) {
        int c = idx / 200, t = idx - c*200;
        int cnt = g_survCnt[b*NC + c];
        if (t < cnt) {
            sval[idx] = g_survVal[(size_t)(b*NC + c)*KK + t];
            sk[idx]   = g_survK  [(size_t)(b*NC + c)*KK + t];
        } else sval[idx] = NEGINF;
    }
    __syncthreads();
    if (tid >= 32) return;
    int lane = tid;
    int c0 = lane, c1 = lane + 32, c2 = lane + 64;
    int h0 = 0, h1 = 0, h2 = 0;
    float v0 = (c0 < NC) ? sval[c0*200] : NEGINF;
    float v1 = (c1 < NC) ? sval[c1*200] : NEGINF;
    float v2 = (c2 < NC) ? sval[c2*200] : NEGINF;
    for (int it = 0; it < DD; it++) {
        float bv = v0; int bc = c0;
        if (v1 > bv) { bv = v1; bc = c1; }
        if (v2 > bv) { bv = v2; bc = c2; }
        for (int o = 16; o > 0; o >>= 1) {
            float ov = __shfl_down_sync(0xFFFFFFFFu, bv, o);
            int   oc = __shfl_down_sync(0xFFFFFFFFu, bc, o);
            if (ov > bv || (ov == bv && oc < bc)) { bv = ov; bc = oc; }
        }
        bv = __shfl_sync(0xFFFFFFFFu, bv, 0);
        bc = __shfl_sync(0xFFFFFFFFu, bc, 0);
        if (bv <= -1e29f) {
            if (lane == 0) for (int r = it; r < DD; r++) g_keepFlat[b*DD + r] = -1;
            return;
        }
        if (lane == (bc & 31)) {
            int slot = bc >> 5;
            int h = (slot == 0) ? h0 : ((slot == 1) ? h1 : h2);
            int kkv = sk[bc*200 + h];
            g_keepFlat[b*DD + it] = bc*KK + kkv;
            h++;
            float nv = (h < 200) ? sval[bc*200 + h] : NEGINF;
            if (slot == 0)      { h0 = h; v0 = nv; }
            else if (slot == 1) { h1 = h; v1 = nv; }
            else                { h2 = h; v2 = nv; }
        }
        __syncwarp();
    }
}

// ---------------- kernel 6: output assembly (one warp per kept row) ----------------
__global__ void output_kernel(float* __restrict__ out, int mode) {
    int wg   = blockIdx.x * (blockDim.x >> 5) + (threadIdx.x >> 5);
    int lane = threadIdx.x & 31;
    if (wg >= BB*DD) return;
    int b = wg / DD, r = wg % DD;
    float* ob = 0; float* os = 0; float* ol = 0;
    if (mode == 0) {                 // full concat: boxes | scores | labels
        ob = out + (size_t)(b*DD + r)*4;
        os = out + (size_t)BB*DD*4 + (size_t)(b*DD + r)*2;
        ol = out + (size_t)BB*DD*6 + (size_t)(b*DD + r)*2;
    } else if (mode == 1) {          // boxes only
        ob = out + (size_t)(b*DD + r)*4;
    } else {                         // scores only
        os = out + (size_t)(b*DD + r)*2;
    }
    int flat = g_keepFlat[b*DD + r];
    if (flat < 0) {
        if (lane == 0) {
            if (ob) { ob[0]=0.f; ob[1]=0.f; ob[2]=0.f; ob[3]=0.f; }
            if (os) { os[0]=0.f; os[1]=0.f; }
            if (ol) { ol[0]=0.f; ol[1]=0.f; }
        }
        return;
    }
    size_t co = (size_t)b*NCAND + flat;
    if (lane == 0 && ob) {
        float4 bx = g_candBox[co];
        ob[0] = bx.x; ob[1] = bx.y; ob[2] = bx.z; ob[3] = bx.w;
    }
    if (!os && !ol) return;
    int anchor = g_candIdx[co];
    float va[3]; int ia[3];
#pragma unroll
    for (int s = 0; s < 3; s++) {
        int c = 1 + lane + 32*s;
        if (c <= NC) { va[s] = g_probsT[((size_t)(b*CC + c))*AA + anchor]; ia[s] = c; }
        else         { va[s] = NEGINF; ia[s] = 1 << 20; }
    }
    float f1v = va[0], f2v = NEGINF;
    int   f1i = ia[0], f2i = 1 << 20;
#pragma unroll
    for (int s = 1; s < 3; s++) {
        if (va[s] > f1v)      { f2v = f1v; f2i = f1i; f1v = va[s]; f1i = ia[s]; }
        else if (va[s] > f2v) { f2v = va[s]; f2i = ia[s]; }
    }
    for (int o = 16; o > 0; o >>= 1) {
        float o1v = __shfl_down_sync(0xFFFFFFFFu, f1v, o);
        int   o1i = __shfl_down_sync(0xFFFFFFFFu, f1i, o);
        float o2v = __shfl_down_sync(0xFFFFFFFFu, f2v, o);
        int   o2i = __shfl_down_sync(0xFFFFFFFFu, f2i, o);
        bool a_first = (f1v > o1v) || (f1v == o1v && f1i < o1i);
        float n1v, n2v; int n1i, n2i;
        if (a_first) {
            n1v = f1v; n1i = f1i;
            bool pick = (f2v > o1v) || (f2v == o1v && f2i < o1i);
            n2v = pick ? f2v : o1v; n2i = pick ? f2i : o1i;
        } else {
            n1v = o1v; n1i = o1i;
            bool pick = (o2v > f1v) || (o2v == f1v && o2i < f1i);
            n2v = pick ? o2v : f1v; n2i = pick ? o2i : f1i;
        }
        f1v = n1v; f1i = n1i; f2v = n2v; f2i = n2i;
    }
    if (lane == 0) {
        if (os) { os[0] = f1v; os[1] = f2v; }
        if (ol) { ol[0] = (float)f1i; ol[1] = (float)f2i; }
    }
}

// ---------------- launcher ----------------
extern "C" void kernel_launch(void* const* d_in, const int* in_sizes, int n_in,
                              void* d_out, int out_size) {
    const float* logits  = (const float*)d_in[0];   // (B, A, C)
    const float* rel     = (const float*)d_in[1];   // (B, A, 4)
    const float* anchors = (const float*)d_in[2];   // (A, 4)
    float* out = (float*)d_out;

    decode_kernel<<<(BB*AA + 127)/128, 128>>>(rel, anchors);

    dim3 gs((AA + 127)/128, BB);
    softmax_kernel<<<gs, 128>>>(logits);

    dim3 gt(NC, BB);
    topk_kernel<<<gt, 256>>>();

    classnms_kernel<<<(BB*NC)/4, 128>>>();

    (void)cudaFuncSetAttribute(merge_kernel,
                               cudaFuncAttributeMaxDynamicSharedMemorySize,
                               NC*200*8);
    merge_kernel<<<BB, 256, NC*200*8>>>();

    int mode = 0;
    if (out_size == BB*DD*8)      mode = 0;  // 25600: boxes|scores|labels
    else if (out_size == BB*DD*4) mode = 1;  // boxes only
    else                          mode = 2;  // scores only fallback
    output_kernel<<<(BB*DD)/8, 256>>>(out, mode);
}

// round 3
// speedup vs baseline: 2.0320x; 1.4497x over previous
#include <cuda_runtime.h>
#include <math.h>

#define BB 16
#define AA 8732
#define CC 91
#define NC 90
#define KK 400
#define KK2 416          /* padded to 13 full warps */
#define NWRD 13
#define NCAND (NC*KK)
#define DD 200
#define IMGV 300.0f
#define OFFV 302.0f
#define THRESH 0.01f
#define NMSV 0.45f
#define NEGINF (-1e30f)
#define CLIPV 4.135166556742356f

// ---------------- scratch (device globals; no allocation) ----------------
__device__ float  g_probsT[(size_t)BB*CC*AA];
__device__ float4 g_boxes[BB*AA];
__device__ float  g_candVal[BB*NCAND];
__device__ int    g_candIdx[BB*NCAND];
__device__ float4 g_candBox[BB*NCAND];
__device__ float  g_survVal[(size_t)BB*NC*KK];
__device__ int    g_survK[(size_t)BB*NC*KK];
__device__ int    g_survCnt[BB*NC];
__device__ int    g_keepFlat[BB*DD];

// ---------------- kernel 1: box decode ----------------
__global__ void decode_kernel(const float* __restrict__ rel,
                              const float* __restrict__ anchors) {
    int i = blockIdx.x * blockDim.x + threadIdx.x;
    if (i >= BB*AA) return;
    int a = i % AA;
    float4 an = ((const float4*)anchors)[a];
    float4 rg = ((const float4*)rel)[i];
    float wa  = __fsub_rn(an.z, an.x);
    float ha  = __fsub_rn(an.w, an.y);
    float cxa = __fadd_rn(an.x, __fmul_rn(0.5f, wa));
    float cya = __fadd_rn(an.y, __fmul_rn(0.5f, ha));
    float dx  = __fdiv_rn(rg.x, 10.0f);
    float dy  = __fdiv_rn(rg.y, 10.0f);
    float dw  = fminf(__fdiv_rn(rg.z, 5.0f), CLIPV);
    float dh  = fminf(__fdiv_rn(rg.w, 5.0f), CLIPV);
    float cx  = __fadd_rn(__fmul_rn(dx, wa), cxa);
    float cy  = __fadd_rn(__fmul_rn(dy, ha), cya);
    float w   = __fmul_rn(expf(dw), wa);
    float h   = __fmul_rn(expf(dh), ha);
    float4 o;
    o.x = fminf(fmaxf(__fsub_rn(cx, __fmul_rn(0.5f, w)), 0.0f), IMGV);
    o.y = fminf(fmaxf(__fsub_rn(cy, __fmul_rn(0.5f, h)), 0.0f), IMGV);
    o.z = fminf(fmaxf(__fadd_rn(cx, __fmul_rn(0.5f, w)), 0.0f), IMGV);
    o.w = fminf(fmaxf(__fadd_rn(cy, __fmul_rn(0.5f, h)), 0.0f), IMGV);
    g_boxes[i] = o;
}

// ---------------- kernel 2: softmax, transposed store ----------------
__global__ void softmax_kernel(const float* __restrict__ logits) {
    __shared__ float s[CC * 129];
    int b = blockIdx.y;
    int a0 = blockIdx.x * 128;
    int na = AA - a0; if (na > 128) na = 128;
    int tid = threadIdx.x;
    const float* base = logits + (size_t)(b*AA + a0) * CC;
    for (int idx = tid; idx < na * CC; idx += 128) {
        int al = idx / CC;
        int c  = idx - al * CC;
        s[c * 129 + al] = base[idx];
    }
    __syncthreads();
    if (tid < na) {
        float m = NEGINF;
        for (int c = 0; c < CC; c++) m = fmaxf(m, s[c*129 + tid]);
        float sum = 0.0f;
        for (int c = 0; c < CC; c++) {
            float e = expf(__fsub_rn(s[c*129 + tid], m));
            s[c*129 + tid] = e;
            sum = __fadd_rn(sum, e);
        }
        for (int c = 0; c < CC; c++)
            s[c*129 + tid] = __fdiv_rn(s[c*129 + tid], sum);
    }
    __syncthreads();
    for (int c = 0; c < CC; c++) {
        if (tid < na)
            g_probsT[((size_t)(b*CC + c))*AA + a0 + tid] = s[c*129 + tid];
    }
}

// ---------------- kernel 3: per-(b,class) top-400 ----------------
__global__ void topk_kernel() {
    __shared__ unsigned keys[AA];
    __shared__ unsigned long long sel[512];
    __shared__ int hist[256];
    __shared__ unsigned s_prefix, s_pmask;
    __shared__ int s_need, s_nsel, s_neq;
    int crow = blockIdx.x;   // class-1
    int b    = blockIdx.y;
    int tid  = threadIdx.x;

    const float* col = g_probsT + ((size_t)(b*CC + crow + 1)) * AA;
    for (int a = tid; a < AA; a += 256) {
        float p = col[a];
        float mval = (p > THRESH) ? p : -1.0f;
        unsigned u = __float_as_uint(mval);
        keys[a] = (u & 0x80000000u) ? ~u : (u | 0x80000000u);
    }
    if (tid == 0) { s_prefix = 0; s_pmask = 0; s_need = KK; s_nsel = 0; s_neq = 0; }
    __syncthreads();

    for (int pass = 0; pass < 4; pass++) {
        int shift = 24 - 8*pass;
        if (tid < 256) hist[tid] = 0;
        __syncthreads();
        unsigned pm = s_pmask, pf = s_prefix;
        for (int a = tid; a < AA; a += 256) {
            unsigned k = keys[a];
            if ((k & pm) == pf) atomicAdd(&hist[(k >> shift) & 255], 1);
        }
        __syncthreads();
        if (tid == 0) {
            int cum = 0, need = s_need;
            for (int d = 255; d >= 0; --d) {
                int h = hist[d];
                if (cum + h >= need) {
                    s_prefix = pf | ((unsigned)d << shift);
                    s_pmask  = pm | (255u << shift);
                    s_need   = need - cum;
                    break;
                }
                cum += h;
            }
        }
        __syncthreads();
    }
    unsigned V = s_prefix;
    int needT  = s_need;

    for (int a = tid; a < AA; a += 256) {
        unsigned k = keys[a];
        if (k > V) {
            int pos = atomicAdd(&s_nsel, 1);
            sel[pos] = ((unsigned long long)k << 32) | (unsigned)(0xFFFFFFFFu - (unsigned)a);
        } else if (k == V) {
            int e = atomicAdd(&s_neq, 1);
            if (e < needT) {
                int pos = atomicAdd(&s_nsel, 1);
                sel[pos] = ((unsigned long long)k << 32) | (unsigned)(0xFFFFFFFFu - (unsigned)a);
            }
        }
    }
    __syncthreads();
    int nsel = s_nsel;
    for (int p = nsel + tid; p < 512; p += 256) sel[p] = 0ULL;
    __syncthreads();

    for (int k2 = 2; k2 <= 512; k2 <<= 1) {
        for (int j = k2 >> 1; j > 0; j >>= 1) {
            for (int i = tid; i < 512; i += 256) {
                int l = i ^ j;
                if (l > i) {
                    unsigned long long x = sel[i], y = sel[l];
                    bool desc = ((i & k2) == 0);
                    if (desc ? (x < y) : (x > y)) { sel[i] = y; sel[l] = x; }
                }
            }
            __syncthreads();
        }
    }

    for (int k = tid; k < KK; k += 256) {
        unsigned long long e = sel[k];
        unsigned vk = (unsigned)(e >> 32);
        unsigned a  = 0xFFFFFFFFu - (unsigned)(e & 0xFFFFFFFFu);
        unsigned u  = (vk & 0x80000000u) ? (vk & 0x7FFFFFFFu) : ~vk;
        float val   = __uint_as_float(u);
        size_t o = (size_t)b*NCAND + crow*KK + k;
        if (k < nsel && a < AA) {
            g_candVal[o] = val;
            g_candIdx[o] = (int)a;
            g_candBox[o] = g_boxes[(size_t)b*AA + a];
        } else {
            g_candVal[o] = -1.0f;
            g_candIdx[o] = 0;
            g_candBox[o] = make_float4(0.f,0.f,0.f,0.f);
        }
    }
}

// ---------------- kernel 4: matrix-NMS per (b,class) ----------------
// One block (8 warps) per (b,class). Phase A: all upper-triangle IoU
// suppression bits computed in parallel (32x32 tiles, ballot per row), FDIV
// replaced by a guarded multiply test (exact div only in the +-0.002 band,
// behind a warp-uniform branch). Phase B: one warp greedy bit-walk: pick
// lowest alive index, clear it and its suppressees. Iterations == survivors.
__global__ void __launch_bounds__(256) classnms_kernel() {
    __shared__ float s_x1[KK2], s_y1[KK2], s_x2[KK2], s_y2[KK2], s_ar[KK2], s_val[KK2];
    __shared__ unsigned s_M[KK2*NWRD];   // row i, word tj
    __shared__ int s_n;
    const unsigned FULL = 0xFFFFFFFFu;
    int tid  = threadIdx.x;
    int wid  = tid >> 5;
    int lane = tid & 31;
    int bi   = blockIdx.x;
    int b    = bi / NC;
    int crow = bi % NC;
    size_t base  = (size_t)b*NCAND + (size_t)crow*KK;
    size_t sbase = (size_t)(b*NC + crow)*KK;
    float off = __fmul_rn((float)(crow + 1), OFFV);

    for (int j = tid; j < KK2; j += 256) {
        float4 bx = make_float4(0.f,0.f,0.f,0.f);
        float v = -1.0f;
        if (j < KK) { bx = g_candBox[base + j]; v = g_candVal[base + j]; }
        float o0 = __fadd_rn(bx.x, off);
        float o1 = __fadd_rn(bx.y, off);
        float o2 = __fadd_rn(bx.z, off);
        float o3 = __fadd_rn(bx.w, off);
        s_x1[j] = o0; s_y1[j] = o1; s_x2[j] = o2; s_y2[j] = o3;
        s_ar[j] = __fmul_rn(__fsub_rn(o2, o0), __fsub_rn(o3, o1));
        s_val[j] = v;
    }
    __syncthreads();

    // n = number of candidates with val > THRESH (sorted desc)
    if (wid == 0) {
        int n = KK;
#pragma unroll
        for (int t = 0; t < NWRD; t++) {
            int j = t*32 + lane;
            bool ok = (j < KK) && (s_val[j] > THRESH);
            unsigned m = __ballot_sync(FULL, ok);
            if (m != FULL) { n = t*32 + __ffs(~m) - 1; break; }
        }
        if (lane == 0) s_n = n;
    }
    __syncthreads();
    int n  = s_n;
    int nw = (n + 31) >> 5;

    // -------- Phase A: suppression-bit matrix --------
    {
        int tt = 0;
        for (int ti = 0; ti < nw; ti++) {
            for (int tj = ti; tj < nw; tj++, tt++) {
                if ((tt & 7) != wid) continue;
                int j = tj*32 + lane;
                float jx1 = s_x1[j], jy1 = s_y1[j];
                float jx2 = s_x2[j], jy2 = s_y2[j];
                float ja  = s_ar[j];
                int i0 = ti*32;
#pragma unroll 4
                for (int ii = 0; ii < 32; ii++) {
                    int i = i0 + ii;
                    float px1 = s_x1[i], py1 = s_y1[i];
                    float px2 = s_x2[i], py2 = s_y2[i];
                    float pa  = s_ar[i];
                    float dx = __fsub_rn(fminf(px2, jx2), fmaxf(px1, jx1));
                    float dy = __fsub_rn(fminf(py2, jy2), fmaxf(py1, jy1));
                    float inter = __fmul_rn(fmaxf(dx, 0.0f), fmaxf(dy, 0.0f));
                    float denom = __fadd_rn(__fsub_rn(__fadd_rn(pa, ja), inter), 1e-9f);
                    bool hi = inter > __fmul_rn(0.451f, denom);
                    bool lo = inter > __fmul_rn(0.449f, denom);
                    bool s  = hi;
                    bool band = lo && !hi;
                    if (__any_sync(FULL, band)) {
                        if (band) s = __fdiv_rn(inter, denom) > NMSV;
                    }
                    if (ti == tj) s = s && (lane > ii);
                    unsigned m = __ballot_sync(FULL, s);
                    if (lane == 0) s_M[i*NWRD + tj] = m;
                }
            }
        }
    }
    __syncthreads();

    // -------- Phase B: greedy bit-walk (warp 0) --------
    if (wid == 0) {
        unsigned alive = 0;
        if (lane < nw) {
            int lo0 = lane*32;
            int nb = n - lo0;
            alive = (nb >= 32) ? FULL : ((nb > 0) ? ((1u << nb) - 1u) : 0u);
        }
        int cnt = 0;
        while (cnt < DD) {
            unsigned act = __ballot_sync(FULL, alive != 0u);
            if (!act) break;
            int wt = __ffs(act) - 1;
            unsigned aw = __shfl_sync(FULL, alive, wt);
            int bit = __ffs(aw) - 1;
            int i = wt*32 + bit;
            if (lane == 0) {
                g_survVal[sbase + cnt] = s_val[i];
                g_survK  [sbase + cnt] = i;
            }
            cnt++;
            if (lane == wt) alive &= ~(1u << bit);
            unsigned m = (lane < NWRD) ? s_M[i*NWRD + lane] : 0u;
            alive &= ~m;
        }
        if (lane == 0) g_survCnt[b*NC + crow] = cnt;
    }
}

// ---------------- kernel 5: per-image merge of survivor streams ----------------
__global__ void merge_kernel() {
    extern __shared__ char sm[];
    float* sval = (float*)sm;                       // [NC][200]
    int*   sk   = (int*)(sm + NC*200*sizeof(float));// [NC][200]
    int b = blockIdx.x, tid = threadIdx.x;
    for (int idx = tid; idx < NC*200; idx += blockDim.x) {
        int c = idx / 200, t = idx - c*200;
        int cnt = g_survCnt[b*NC + c];
        if (t < cnt) {
            sval[idx] = g_survVal[(size_t)(b*NC + c)*KK + t];
            sk[idx]   = g_survK  [(size_t)(b*NC + c)*KK + t];
        } else sval[idx] = NEGINF;
    }
    __syncthreads();
    if (tid >= 32) return;
    int lane = tid;
    int c0 = lane, c1 = lane + 32, c2 = lane + 64;
    int h0 = 0, h1 = 0, h2 = 0;
    float v0 = (c0 < NC) ? sval[c0*200] : NEGINF;
    float v1 = (c1 < NC) ? sval[c1*200] : NEGINF;
    float v2 = (c2 < NC) ? sval[c2*200] : NEGINF;
    for (int it = 0; it < DD; it++) {
        float bv = v0; int bc = c0;
        if (v1 > bv) { bv = v1; bc = c1; }
        if (v2 > bv) { bv = v2; bc = c2; }
        for (int o = 16; o > 0; o >>= 1) {
            float ov = __shfl_down_sync(0xFFFFFFFFu, bv, o);
            int   oc = __shfl_down_sync(0xFFFFFFFFu, bc, o);
            if (ov > bv || (ov == bv && oc < bc)) { bv = ov; bc = oc; }
        }
        bv = __shfl_sync(0xFFFFFFFFu, bv, 0);
        bc = __shfl_sync(0xFFFFFFFFu, bc, 0);
        if (bv <= -1e29f) {
            if (lane == 0) for (int r = it; r < DD; r++) g_keepFlat[b*DD + r] = -1;
            return;
        }
        if (lane == (bc & 31)) {
            int slot = bc >> 5;
            int h = (slot == 0) ? h0 : ((slot == 1) ? h1 : h2);
            int kkv = sk[bc*200 + h];
            g_keepFlat[b*DD + it] = bc*KK + kkv;
            h++;
            float nv = (h < 200) ? sval[bc*200 + h] : NEGINF;
            if (slot == 0)      { h0 = h; v0 = nv; }
            else if (slot == 1) { h1 = h; v1 = nv; }
            else                { h2 = h; v2 = nv; }
        }
        __syncwarp();
    }
}

// ---------------- kernel 6: output assembly ----------------
__global__ void output_kernel(float* __restrict__ out, int mode) {
    int wg   = blockIdx.x * (blockDim.x >> 5) + (threadIdx.x >> 5);
    int lane = threadIdx.x & 31;
    if (wg >= BB*DD) return;
    int b = wg / DD, r = wg % DD;
    float* ob = 0; float* os = 0; float* ol = 0;
    if (mode == 0) {
        ob = out + (size_t)(b*DD + r)*4;
        os = out + (size_t)BB*DD*4 + (size_t)(b*DD + r)*2;
        ol = out + (size_t)BB*DD*6 + (size_t)(b*DD + r)*2;
    } else if (mode == 1) {
        ob = out + (size_t)(b*DD + r)*4;
    } else {
        os = out + (size_t)(b*DD + r)*2;
    }
    int flat = g_keepFlat[b*DD + r];
    if (flat < 0) {
        if (lane == 0) {
            if (ob) { ob[0]=0.f; ob[1]=0.f; ob[2]=0.f; ob[3]=0.f; }
            if (os) { os[0]=0.f; os[1]=0.f; }
            if (ol) { ol[0]=0.f; ol[1]=0.f; }
        }
        return;
    }
    size_t co = (size_t)b*NCAND + flat;
    if (lane == 0 && ob) {
        float4 bx = g_candBox[co];
        ob[0] = bx.x; ob[1] = bx.y; ob[2] = bx.z; ob[3] = bx.w;
    }
    if (!os && !ol) return;
    int anchor = g_candIdx[co];
    float va[3]; int ia[3];
#pragma unroll
    for (int s = 0; s < 3; s++) {
        int c = 1 + lane + 32*s;
        if (c <= NC) { va[s] = g_probsT[((size_t)(b*CC + c))*AA + anchor]; ia[s] = c; }
        else         { va[s] = NEGINF; ia[s] = 1 << 20; }
    }
    float f1v = va[0], f2v = NEGINF;
    int   f1i = ia[0], f2i = 1 << 20;
#pragma unroll
    for (int s = 1; s < 3; s++) {
        if (va[s] > f1v)      { f2v = f1v; f2i = f1i; f1v = va[s]; f1i = ia[s]; }
        else if (va[s] > f2v) { f2v = va[s]; f2i = ia[s]; }
    }
    for (int o = 16; o > 0; o >>= 1) {
        float o1v = __shfl_down_sync(0xFFFFFFFFu, f1v, o);
        int   o1i = __shfl_down_sync(0xFFFFFFFFu, f1i, o);
        float o2v = __shfl_down_sync(0xFFFFFFFFu, f2v, o);
        int   o2i = __shfl_down_sync(0xFFFFFFFFu, f2i, o);
        bool a_first = (f1v > o1v) || (f1v == o1v && f1i < o1i);
        float n1v, n2v; int n1i, n2i;
        if (a_first) {
            n1v = f1v; n1i = f1i;
            bool pick = (f2v > o1v) || (f2v == o1v && f2i < o1i);
            n2v = pick ? f2v : o1v; n2i = pick ? f2i : o1i;
        } else {
            n1v = o1v; n1i = o1i;
            bool pick = (o2v > f1v) || (o2v == f1v && o2i < f1i);
            n2v = pick ? o2v : f1v; n2i = pick ? o2i : f1i;
        }
        f1v = n1v; f1i = n1i; f2v = n2v; f2i = n2i;
    }
    if (lane == 0) {
        if (os) { os[0] = f1v; os[1] = f2v; }
        if (ol) { ol[0] = (float)f1i; ol[1] = (float)f2i; }
    }
}

// ---------------- launcher ----------------
extern "C" void kernel_launch(void* const* d_in, const int* in_sizes, int n_in,
                              void* d_out, int out_size) {
    const float* logits  = (const float*)d_in[0];   // (B, A, C)
    const float* rel     = (const float*)d_in[1];   // (B, A, 4)
    const float* anchors = (const float*)d_in[2];   // (A, 4)
    float* out = (float*)d_out;

    decode_kernel<<<(BB*AA + 127)/128, 128>>>(rel, anchors);

    dim3 gs((AA + 127)/128, BB);
    softmax_kernel<<<gs, 128>>>(logits);

    dim3 gt(NC, BB);
    topk_kernel<<<gt, 256>>>();

    classnms_kernel<<<BB*NC, 256>>>();

    (void)cudaFuncSetAttribute(merge_kernel,
                               cudaFuncAttributeMaxDynamicSharedMemorySize,
                               NC*200*8);
    merge_kernel<<<BB, 256, NC*200*8>>>();

    int mode = 0;
    if (out_size == BB*DD*8)      mode = 0;
    else if (out_size == BB*DD*4) mode = 1;
    else                          mode = 2;
    output_kernel<<<(BB*DD)/8, 256>>>(out, mode);
}